// round 11
// baseline (speedup 1.0000x reference)
#include <cuda_runtime.h>
#include <cuda_fp16.h>
#include <math.h>

#define NN   100000
#define EE   1600000
#define ETOT (EE + NN)
#define INC  128
#define HC   128     // HEADS*OUT_C
#define OC   32
#define HEADS 4
#define NEG_SLOPE 0.2f
#define SCAN_BLK 256
#define XS_STRIDE 68

typedef unsigned long long u64;

// ---------------- device scratch (static: no allocations allowed) ----------
__device__ int    g_esrc[ETOT];          // CSR: src ids grouped by dst
__device__ int    g_deg[NN];             // in-degree per node
__device__ int    g_tmp[NN];             // block-local exclusive scan
__device__ int    g_part[1024];          // per-block partial sums
__device__ int    g_rowptr[NN];          // CSR row starts
__device__ int    g_cursor[NN];          // scatter cursors
__device__ __half g_h[NN * HC];          // projected features, fp16 [N,128]
__device__ float  g_as[NN * HEADS];      // per-node src logits (fp32)
__device__ float  g_ad[NN * HEADS];      // per-node dst logits (fp32)

// ---------------- packed f32x2 helpers --------------------------------------
__device__ __forceinline__ u64 pk2(float a, float b) {
    u64 r; asm("mov.b64 %0, {%1, %2};" : "=l"(r) : "f"(a), "f"(b)); return r;
}
__device__ __forceinline__ void fma2(u64& d, u64 a, u64 b) {
    asm("fma.rn.f32x2 %0, %1, %2, %0;" : "+l"(d) : "l"(a), "l"(b));
}
__device__ __forceinline__ float2 up2(u64 v) {
    float2 r; asm("mov.b64 {%0, %1}, %2;" : "=f"(r.x), "=f"(r.y) : "l"(v)); return r;
}
__device__ __forceinline__ unsigned int f2h2(float a, float b) {
    __half2 h = __floats2half2_rn(a, b);
    return *(unsigned int*)&h;
}

// per-call dtype detection: reads first 64 entries as int64; all-valid => i64
__device__ __forceinline__ int detect64(const void* ei) {
    const long long* p = (const long long*)ei;
    int ok = 1;
    #pragma unroll 1
    for (int q = 0; q < 64; ++q) {
        long long v = p[q];
        if (!(v >= 0 && v < (long long)NN)) { ok = 0; break; }
    }
    return ok;
}

// ---------------- histogram in-degrees --------------------------------------
__global__ void k_prep(const void* ei, int e, int n) {
    int is64 = detect64(ei);
    int i = blockIdx.x * blockDim.x + threadIdx.x;
    int tot = e + n;
    if (i >= tot) return;
    int d;
    if (i < e) {
        if (is64) d = (int)((const long long*)ei)[e + i];
        else      d = ((const int*)ei)[e + i];
    } else {
        d = i - e;
    }
    atomicAdd(&g_deg[d], 1);
}

// ---------------- scan stage 1 ----------------------------------------------
__global__ void k_scan1(int n) {
    __shared__ int sm[SCAN_BLK];
    int t = threadIdx.x;
    int i = blockIdx.x * SCAN_BLK + t;
    int v = (i < n) ? g_deg[i] : 0;
    sm[t] = v;
    __syncthreads();
    #pragma unroll
    for (int off = 1; off < SCAN_BLK; off <<= 1) {
        int u = (t >= off) ? sm[t - off] : 0;
        __syncthreads();
        sm[t] += u;
        __syncthreads();
    }
    if (i < n) g_tmp[i] = sm[t] - v;
    if (t == SCAN_BLK - 1) g_part[blockIdx.x] = sm[t];
}

// ---------------- scan stage 2+3 --------------------------------------------
__global__ void k_scan23(int n) {
    __shared__ int sm[SCAN_BLK];
    int b = blockIdx.x, t = threadIdx.x;
    int acc = 0;
    for (int j = t; j < b; j += SCAN_BLK) acc += g_part[j];
    sm[t] = acc;
    __syncthreads();
    #pragma unroll
    for (int off = SCAN_BLK / 2; off > 0; off >>= 1) {
        if (t < off) sm[t] += sm[t + off];
        __syncthreads();
    }
    int base = sm[0];
    int i = b * SCAN_BLK + t;
    if (i < n) {
        int r = g_tmp[i] + base;
        g_rowptr[i] = r;
        g_cursor[i] = r;
    }
}

// ---------------- fused GEMM (+logits) || CSR scatter -----------------------
__global__ void __launch_bounds__(256)
k_gemm_scatter(const float* __restrict__ x, const float* __restrict__ W,
               const float* __restrict__ att_s, const float* __restrict__ att_d,
               const void* ei, int n, int e,
               int nb_gemm, int nb_scat) {
    int bid = blockIdx.x;
    int tid = threadIdx.x;

    if ((bid & 3) == 3) {
        int sid = bid >> 2;
        if (sid >= nb_scat) return;
        int is64 = detect64(ei);
        int etot = e + n;
        int stride = nb_scat * 256;
        for (int i = sid * 256 + tid; i < etot; i += stride) {
            int s, d;
            if (i < e) {
                if (is64) {
                    const long long* p = (const long long*)ei;
                    s = (int)p[i];
                    d = (int)p[e + i];
                } else {
                    const int* p = (const int*)ei;
                    s = p[i];
                    d = p[e + i];
                }
            } else {
                s = d = i - e;
            }
            int pos = atomicAdd(&g_cursor[d], 1);
            g_esrc[pos] = s;
        }
        return;
    }

    int gid = (bid >> 2) * 3 + (bid & 3);
    if (gid >= nb_gemm) return;

    extern __shared__ float smx[];
    float* Ws = smx;                        // [128][132]
    float* xs = smx + 128 * 132;            // transposed [128][XS_STRIDE]

    for (int idx = tid; idx < HC * INC; idx += 256) {
        int j = idx >> 7, k = idx & 127;
        Ws[k * 132 + j] = W[idx];
    }
    int row0 = gid * 64;
    for (int idx = tid; idx < 64 * INC; idx += 256) {
        int r = idx >> 7;
        int k = idx & 127;
        float v = (row0 + r < n) ? x[(size_t)row0 * INC + idx] : 0.0f;
        xs[k * XS_STRIDE + r] = v;
    }
    __syncthreads();

    int tx = tid & 31;
    int ty = tid >> 5;

    u64 accp[4][4];
    #pragma unroll
    for (int rp = 0; rp < 4; ++rp)
        #pragma unroll
        for (int c = 0; c < 4; ++c) accp[rp][c] = pk2(0.0f, 0.0f);

    const float* xrow = &xs[ty * 8];
    const float* wbase = &Ws[tx * 4];

    #pragma unroll 4
    for (int k = 0; k < 128; ++k) {
        float4 wv = *(const float4*)&wbase[k * 132];
        u64 wd0 = pk2(wv.x, wv.x);
        u64 wd1 = pk2(wv.y, wv.y);
        u64 wd2 = pk2(wv.z, wv.z);
        u64 wd3 = pk2(wv.w, wv.w);
        ulonglong2 xpa = *(const ulonglong2*)&xrow[k * XS_STRIDE];
        ulonglong2 xpb = *(const ulonglong2*)&xrow[k * XS_STRIDE + 4];
        fma2(accp[0][0], xpa.x, wd0); fma2(accp[0][1], xpa.x, wd1);
        fma2(accp[0][2], xpa.x, wd2); fma2(accp[0][3], xpa.x, wd3);
        fma2(accp[1][0], xpa.y, wd0); fma2(accp[1][1], xpa.y, wd1);
        fma2(accp[1][2], xpa.y, wd2); fma2(accp[1][3], xpa.y, wd3);
        fma2(accp[2][0], xpb.x, wd0); fma2(accp[2][1], xpb.x, wd1);
        fma2(accp[2][2], xpb.x, wd2); fma2(accp[2][3], xpb.x, wd3);
        fma2(accp[3][0], xpb.y, wd0); fma2(accp[3][1], xpb.y, wd1);
        fma2(accp[3][2], xpb.y, wd2); fma2(accp[3][3], xpb.y, wd3);
    }

    float4 asv = *(const float4*)&att_s[tx * 4];
    float4 adv = *(const float4*)&att_d[tx * 4];
    int head = tx >> 3;

    #pragma unroll
    for (int rp = 0; rp < 4; ++rp) {
        float2 p0 = up2(accp[rp][0]);
        float2 p1 = up2(accp[rp][1]);
        float2 p2 = up2(accp[rp][2]);
        float2 p3 = up2(accp[rp][3]);
        int row_e = row0 + ty * 8 + 2 * rp;
        int row_o = row_e + 1;
        if (row_e < n) {
            uint2 pk = make_uint2(f2h2(p0.x, p1.x), f2h2(p2.x, p3.x));
            *(uint2*)&g_h[(size_t)row_e * HC + tx * 4] = pk;
        }
        if (row_o < n) {
            uint2 pk = make_uint2(f2h2(p0.y, p1.y), f2h2(p2.y, p3.y));
            *(uint2*)&g_h[(size_t)row_o * HC + tx * 4] = pk;
        }

        float pse = p0.x * asv.x + p1.x * asv.y + p2.x * asv.z + p3.x * asv.w;
        float pde = p0.x * adv.x + p1.x * adv.y + p2.x * adv.z + p3.x * adv.w;
        float pso = p0.y * asv.x + p1.y * asv.y + p2.y * asv.z + p3.y * asv.w;
        float pdo = p0.y * adv.x + p1.y * adv.y + p2.y * adv.z + p3.y * adv.w;
        #pragma unroll
        for (int o = 4; o > 0; o >>= 1) {
            pse += __shfl_xor_sync(0xffffffffu, pse, o);
            pde += __shfl_xor_sync(0xffffffffu, pde, o);
            pso += __shfl_xor_sync(0xffffffffu, pso, o);
            pdo += __shfl_xor_sync(0xffffffffu, pdo, o);
        }
        if ((tx & 7) == 0) {
            if (row_e < n) { g_as[row_e * HEADS + head] = pse; g_ad[row_e * HEADS + head] = pde; }
            if (row_o < n) { g_as[row_o * HEADS + head] = pso; g_ad[row_o * HEADS + head] = pdo; }
        }
    }
}

// ---------------- fused gather + final linear --------------------------------
// 512 threads = 16 warps = 16 nodes/block. Half-warp edge parallelism:
// lanes 0-15 process edge j, lanes 16-31 edge j+1; each lane loads uint4
// (8 fp16 channels). 1.5 warp-LDG/edge instead of 3. Merge via shfl_xor(16).
__global__ void __launch_bounds__(512, 2)
k_gather_final(const float* __restrict__ bias,
               const float* __restrict__ Wl,
               const float* __restrict__ bl,
               float* __restrict__ out, int n) {
    __shared__ __half2 Wt2[64 * 32];  // Wt2[kp*32+oc]
    __shared__ float xr[16][128];
    int tid  = threadIdx.x;
    int warp = tid >> 5;
    int lane = tid & 31;
    int half = lane >> 4;             // 0: even edges, 1: odd edges
    int hl   = lane & 15;
    int chb  = hl * 8;                // channel base (8 fp16 per lane)
    int hh   = hl >> 2;               // head = chb/32
    int node = blockIdx.x * 16 + warp;

    for (int idx = tid; idx < OC * HC / 2; idx += 512) {
        int oc = idx >> 6;
        int kp = idx & 63;
        Wt2[kp * 32 + oc] = __floats2half2_rn(Wl[oc * HC + 2 * kp],
                                              Wl[oc * HC + 2 * kp + 1]);
    }
    __syncthreads();
    if (node >= n) return;

    int start = g_rowptr[node];
    int deg   = g_deg[node];
    float adv = g_ad[node * HEADS + hh];
    const int* es = &g_esrc[start];
    const __half* hbase = g_h;

    float sum = 0.0f;
    float acc[8];
    #pragma unroll
    for (int i = 0; i < 8; ++i) acc[i] = 0.0f;

    #pragma unroll 2
    for (int j = 0; j < deg; j += 2) {
        int jj = j + half;
        bool v = jj < deg;
        int s = __ldg(es + (v ? jj : j));
        float a = g_as[s * HEADS + hh];
        uint4 hv = *(const uint4*)&hbase[(size_t)s * HC + chb];
        float e0 = a + adv;
        e0 = e0 > 0.f ? e0 : NEG_SLOPE * e0;
        float w = v ? __expf(e0) : 0.0f;
        sum += w;
        float2 c0 = __half22float2(*(const __half2*)&hv.x);
        float2 c1 = __half22float2(*(const __half2*)&hv.y);
        float2 c2 = __half22float2(*(const __half2*)&hv.z);
        float2 c3 = __half22float2(*(const __half2*)&hv.w);
        acc[0] = fmaf(w, c0.x, acc[0]);
        acc[1] = fmaf(w, c0.y, acc[1]);
        acc[2] = fmaf(w, c1.x, acc[2]);
        acc[3] = fmaf(w, c1.y, acc[3]);
        acc[4] = fmaf(w, c2.x, acc[4]);
        acc[5] = fmaf(w, c2.y, acc[5]);
        acc[6] = fmaf(w, c3.x, acc[6]);
        acc[7] = fmaf(w, c3.y, acc[7]);
    }

    // merge halves (even+odd edge partial sums)
    sum += __shfl_xor_sync(0xffffffffu, sum, 16);
    #pragma unroll
    for (int i = 0; i < 8; ++i)
        acc[i] += __shfl_xor_sync(0xffffffffu, acc[i], 16);

    float inv = 1.0f / sum;
    if (half == 0) {
        float4 b0 = *(const float4*)&bias[chb];
        float4 b1 = *(const float4*)&bias[chb + 4];
        xr[warp][chb + 0] = fmaf(acc[0], inv, b0.x);
        xr[warp][chb + 1] = fmaf(acc[1], inv, b0.y);
        xr[warp][chb + 2] = fmaf(acc[2], inv, b0.z);
        xr[warp][chb + 3] = fmaf(acc[3], inv, b0.w);
        xr[warp][chb + 4] = fmaf(acc[4], inv, b1.x);
        xr[warp][chb + 5] = fmaf(acc[5], inv, b1.y);
        xr[warp][chb + 6] = fmaf(acc[6], inv, b1.z);
        xr[warp][chb + 7] = fmaf(acc[7], inv, b1.w);
    }
    __syncwarp();

    int oc = lane;
    float accv = 0.0f;
    const float* row = xr[warp];
    #pragma unroll 8
    for (int kp = 0; kp < 64; ++kp) {
        float2 wv = __half22float2(Wt2[kp * 32 + oc]);
        accv = fmaf(row[2 * kp], wv.x, accv);
        accv = fmaf(row[2 * kp + 1], wv.y, accv);
    }
    accv += __ldg(&bl[oc]);
    out[(size_t)node * OC + oc] = accv > 0.0f ? accv : (__expf(accv) - 1.0f);
}

// ---------------- launch -----------------------------------------------------
extern "C" void kernel_launch(void* const* d_in, const int* in_sizes, int n_in,
                              void* d_out, int out_size) {
    const float* x     = (const float*)d_in[0];
    const void*  ei    = d_in[1];
    const float* W     = (const float*)d_in[2];
    const float* att_s = (const float*)d_in[3];
    const float* att_d = (const float*)d_in[4];
    const float* bias  = (const float*)d_in[5];
    const float* Wl    = (const float*)d_in[6];
    const float* bl    = (const float*)d_in[7];
    float* out = (float*)d_out;

    int n = in_sizes[0] / INC;
    int e = in_sizes[1] / 2;
    int etot = e + n;
    int nscan = (n + SCAN_BLK - 1) / SCAN_BLK;

    int nb_gemm = (n + 63) / 64;
    int nb_scat = (nb_gemm + 2) / 3;
    int nb_fused = 4 * nb_scat;

    static void* deg_ptr = nullptr;
    static int smem_set = 0;
    if (!smem_set) {
        cudaFuncSetAttribute(k_gemm_scatter, cudaFuncAttributeMaxDynamicSharedMemorySize, 110 * 1024);
        cudaGetSymbolAddress(&deg_ptr, g_deg);
        smem_set = 1;
    }
    size_t gemm_smem = (size_t)(128 * 132 + 128 * XS_STRIDE) * sizeof(float);

    cudaMemsetAsync(deg_ptr, 0, (size_t)n * sizeof(int));
    k_prep<<<(etot + 255) / 256, 256>>>(ei, e, n);
    k_scan1<<<nscan, SCAN_BLK>>>(n);
    k_scan23<<<nscan, SCAN_BLK>>>(n);
    k_gemm_scatter<<<nb_fused, 256, gemm_smem>>>(x, W, att_s, att_d, ei, n, e, nb_gemm, nb_scat);
    k_gather_final<<<(n + 15) / 16, 512>>>(bias, Wl, bl, out, n);
}

// round 12
// speedup vs baseline: 1.2175x; 1.2175x over previous
#include <cuda_runtime.h>
#include <cuda_fp16.h>
#include <math.h>

#define NN   100000
#define EE   1600000
#define ETOT (EE + NN)
#define INC  128
#define HC   128     // HEADS*OUT_C
#define OC   32
#define HEADS 4
#define NEG_SLOPE 0.2f
#define SCAN_BLK 256
#define XS_STRIDE 68
#define GATHER_BLOCKS 304   // 2 per SM on 152 SMs

typedef unsigned long long u64;

// ---------------- device scratch (static: no allocations allowed) ----------
__device__ int    g_esrc[ETOT];          // CSR: src ids grouped by dst
__device__ int    g_deg[NN];             // in-degree per node
__device__ int    g_tmp[NN];             // block-local exclusive scan
__device__ int    g_part[1024];          // per-block partial sums
__device__ int    g_rowptr[NN];          // CSR row starts
__device__ int    g_cursor[NN];          // scatter cursors
__device__ __half g_h[NN * HC];          // projected features, fp16 [N,128]
__device__ float  g_as[NN * HEADS];      // per-node src logits (fp32)
__device__ float  g_ad[NN * HEADS];      // per-node dst logits (fp32)

// ---------------- packed f32x2 helpers --------------------------------------
__device__ __forceinline__ u64 pk2(float a, float b) {
    u64 r; asm("mov.b64 %0, {%1, %2};" : "=l"(r) : "f"(a), "f"(b)); return r;
}
__device__ __forceinline__ void fma2(u64& d, u64 a, u64 b) {
    asm("fma.rn.f32x2 %0, %1, %2, %0;" : "+l"(d) : "l"(a), "l"(b));
}
__device__ __forceinline__ float2 up2(u64 v) {
    float2 r; asm("mov.b64 {%0, %1}, %2;" : "=f"(r.x), "=f"(r.y) : "l"(v)); return r;
}
__device__ __forceinline__ unsigned int f2h2(float a, float b) {
    __half2 h = __floats2half2_rn(a, b);
    return *(unsigned int*)&h;
}

// per-call dtype detection: reads first 64 entries as int64; all-valid => i64
__device__ __forceinline__ int detect64(const void* ei) {
    const long long* p = (const long long*)ei;
    int ok = 1;
    #pragma unroll 1
    for (int q = 0; q < 64; ++q) {
        long long v = p[q];
        if (!(v >= 0 && v < (long long)NN)) { ok = 0; break; }
    }
    return ok;
}

// ---------------- histogram in-degrees --------------------------------------
__global__ void k_prep(const void* ei, int e, int n) {
    int is64 = detect64(ei);
    int i = blockIdx.x * blockDim.x + threadIdx.x;
    int tot = e + n;
    if (i >= tot) return;
    int d;
    if (i < e) {
        if (is64) d = (int)((const long long*)ei)[e + i];
        else      d = ((const int*)ei)[e + i];
    } else {
        d = i - e;
    }
    atomicAdd(&g_deg[d], 1);
}

// ---------------- scan stage 1 ----------------------------------------------
__global__ void k_scan1(int n) {
    __shared__ int sm[SCAN_BLK];
    int t = threadIdx.x;
    int i = blockIdx.x * SCAN_BLK + t;
    int v = (i < n) ? g_deg[i] : 0;
    sm[t] = v;
    __syncthreads();
    #pragma unroll
    for (int off = 1; off < SCAN_BLK; off <<= 1) {
        int u = (t >= off) ? sm[t - off] : 0;
        __syncthreads();
        sm[t] += u;
        __syncthreads();
    }
    if (i < n) g_tmp[i] = sm[t] - v;
    if (t == SCAN_BLK - 1) g_part[blockIdx.x] = sm[t];
}

// ---------------- scan stage 2+3 --------------------------------------------
__global__ void k_scan23(int n) {
    __shared__ int sm[SCAN_BLK];
    int b = blockIdx.x, t = threadIdx.x;
    int acc = 0;
    for (int j = t; j < b; j += SCAN_BLK) acc += g_part[j];
    sm[t] = acc;
    __syncthreads();
    #pragma unroll
    for (int off = SCAN_BLK / 2; off > 0; off >>= 1) {
        if (t < off) sm[t] += sm[t + off];
        __syncthreads();
    }
    int base = sm[0];
    int i = b * SCAN_BLK + t;
    if (i < n) {
        int r = g_tmp[i] + base;
        g_rowptr[i] = r;
        g_cursor[i] = r;
    }
}

// ---------------- fused GEMM (+logits) || CSR scatter -----------------------
__global__ void __launch_bounds__(256)
k_gemm_scatter(const float* __restrict__ x, const float* __restrict__ W,
               const float* __restrict__ att_s, const float* __restrict__ att_d,
               const void* ei, int n, int e,
               int nb_gemm, int nb_scat) {
    int bid = blockIdx.x;
    int tid = threadIdx.x;

    if ((bid & 3) == 3) {
        int sid = bid >> 2;
        if (sid >= nb_scat) return;
        int is64 = detect64(ei);
        int etot = e + n;
        int stride = nb_scat * 256;
        for (int i = sid * 256 + tid; i < etot; i += stride) {
            int s, d;
            if (i < e) {
                if (is64) {
                    const long long* p = (const long long*)ei;
                    s = (int)p[i];
                    d = (int)p[e + i];
                } else {
                    const int* p = (const int*)ei;
                    s = p[i];
                    d = p[e + i];
                }
            } else {
                s = d = i - e;
            }
            int pos = atomicAdd(&g_cursor[d], 1);
            g_esrc[pos] = s;
        }
        return;
    }

    int gid = (bid >> 2) * 3 + (bid & 3);
    if (gid >= nb_gemm) return;

    extern __shared__ float smx[];
    float* Ws = smx;                        // [128][132]
    float* xs = smx + 128 * 132;            // transposed [128][XS_STRIDE]

    for (int idx = tid; idx < HC * INC; idx += 256) {
        int j = idx >> 7, k = idx & 127;
        Ws[k * 132 + j] = W[idx];
    }
    int row0 = gid * 64;
    for (int idx = tid; idx < 64 * INC; idx += 256) {
        int r = idx >> 7;
        int k = idx & 127;
        float v = (row0 + r < n) ? x[(size_t)row0 * INC + idx] : 0.0f;
        xs[k * XS_STRIDE + r] = v;
    }
    __syncthreads();

    int tx = tid & 31;
    int ty = tid >> 5;

    u64 accp[4][4];
    #pragma unroll
    for (int rp = 0; rp < 4; ++rp)
        #pragma unroll
        for (int c = 0; c < 4; ++c) accp[rp][c] = pk2(0.0f, 0.0f);

    const float* xrow = &xs[ty * 8];
    const float* wbase = &Ws[tx * 4];

    #pragma unroll 4
    for (int k = 0; k < 128; ++k) {
        float4 wv = *(const float4*)&wbase[k * 132];
        u64 wd0 = pk2(wv.x, wv.x);
        u64 wd1 = pk2(wv.y, wv.y);
        u64 wd2 = pk2(wv.z, wv.z);
        u64 wd3 = pk2(wv.w, wv.w);
        ulonglong2 xpa = *(const ulonglong2*)&xrow[k * XS_STRIDE];
        ulonglong2 xpb = *(const ulonglong2*)&xrow[k * XS_STRIDE + 4];
        fma2(accp[0][0], xpa.x, wd0); fma2(accp[0][1], xpa.x, wd1);
        fma2(accp[0][2], xpa.x, wd2); fma2(accp[0][3], xpa.x, wd3);
        fma2(accp[1][0], xpa.y, wd0); fma2(accp[1][1], xpa.y, wd1);
        fma2(accp[1][2], xpa.y, wd2); fma2(accp[1][3], xpa.y, wd3);
        fma2(accp[2][0], xpb.x, wd0); fma2(accp[2][1], xpb.x, wd1);
        fma2(accp[2][2], xpb.x, wd2); fma2(accp[2][3], xpb.x, wd3);
        fma2(accp[3][0], xpb.y, wd0); fma2(accp[3][1], xpb.y, wd1);
        fma2(accp[3][2], xpb.y, wd2); fma2(accp[3][3], xpb.y, wd3);
    }

    float4 asv = *(const float4*)&att_s[tx * 4];
    float4 adv = *(const float4*)&att_d[tx * 4];
    int head = tx >> 3;

    #pragma unroll
    for (int rp = 0; rp < 4; ++rp) {
        float2 p0 = up2(accp[rp][0]);
        float2 p1 = up2(accp[rp][1]);
        float2 p2 = up2(accp[rp][2]);
        float2 p3 = up2(accp[rp][3]);
        int row_e = row0 + ty * 8 + 2 * rp;
        int row_o = row_e + 1;
        if (row_e < n) {
            uint2 pk = make_uint2(f2h2(p0.x, p1.x), f2h2(p2.x, p3.x));
            *(uint2*)&g_h[(size_t)row_e * HC + tx * 4] = pk;
        }
        if (row_o < n) {
            uint2 pk = make_uint2(f2h2(p0.y, p1.y), f2h2(p2.y, p3.y));
            *(uint2*)&g_h[(size_t)row_o * HC + tx * 4] = pk;
        }

        float pse = p0.x * asv.x + p1.x * asv.y + p2.x * asv.z + p3.x * asv.w;
        float pde = p0.x * adv.x + p1.x * adv.y + p2.x * adv.z + p3.x * adv.w;
        float pso = p0.y * asv.x + p1.y * asv.y + p2.y * asv.z + p3.y * asv.w;
        float pdo = p0.y * adv.x + p1.y * adv.y + p2.y * adv.z + p3.y * adv.w;
        #pragma unroll
        for (int o = 4; o > 0; o >>= 1) {
            pse += __shfl_xor_sync(0xffffffffu, pse, o);
            pde += __shfl_xor_sync(0xffffffffu, pde, o);
            pso += __shfl_xor_sync(0xffffffffu, pso, o);
            pdo += __shfl_xor_sync(0xffffffffu, pdo, o);
        }
        if ((tx & 7) == 0) {
            if (row_e < n) { g_as[row_e * HEADS + head] = pse; g_ad[row_e * HEADS + head] = pde; }
            if (row_o < n) { g_as[row_o * HEADS + head] = pso; g_ad[row_o * HEADS + head] = pdo; }
        }
    }
}

// ---------------- persistent fused gather + final linear ---------------------
// 304 blocks x 16 warps = 4864 persistent warps; warp gw strides nodes
// gw, gw+4864, ... (~21 nodes each) => degree imbalance averages out,
// no wave transitions. Inner loop = proven R10 structure (4-wide, uint2 fp16).
__global__ void __launch_bounds__(512, 2)
k_gather_final(const float* __restrict__ bias,
               const float* __restrict__ Wl,
               const float* __restrict__ bl,
               float* __restrict__ out, int n, int nwarps) {
    __shared__ __half2 Wt2[64 * 32];  // Wt2[kp*32+oc]
    __shared__ float xr[16][128];
    int tid  = threadIdx.x;
    int warp = tid >> 5;
    int lane = tid & 31;
    int gw   = blockIdx.x * 16 + warp;

    for (int idx = tid; idx < OC * HC / 2; idx += 512) {
        int oc = idx >> 6;
        int kp = idx & 63;
        Wt2[kp * 32 + oc] = __floats2half2_rn(Wl[oc * HC + 2 * kp],
                                              Wl[oc * HC + 2 * kp + 1]);
    }
    __syncthreads();

    int hh = lane >> 3;
    const __half* hbase = g_h;

    for (int node = gw; node < n; node += nwarps) {
        int start = g_rowptr[node];
        int deg   = g_deg[node];
        float adv = g_ad[node * HEADS + hh];
        const int* es = &g_esrc[start];

        float sum = 0.0f;
        float ax = 0.f, ay = 0.f, az = 0.f, aw = 0.f;
        int j = 0;
        for (; j + 4 <= deg; j += 4) {
            int s0 = __ldg(es + j), s1 = __ldg(es + j + 1);
            int s2 = __ldg(es + j + 2), s3 = __ldg(es + j + 3);
            float a0 = g_as[s0 * HEADS + hh];
            float a1 = g_as[s1 * HEADS + hh];
            float a2 = g_as[s2 * HEADS + hh];
            float a3 = g_as[s3 * HEADS + hh];
            uint2 v0 = *(const uint2*)&hbase[(size_t)s0 * HC + lane * 4];
            uint2 v1 = *(const uint2*)&hbase[(size_t)s1 * HC + lane * 4];
            uint2 v2 = *(const uint2*)&hbase[(size_t)s2 * HC + lane * 4];
            uint2 v3 = *(const uint2*)&hbase[(size_t)s3 * HC + lane * 4];
            float e0 = a0 + adv; e0 = e0 > 0.f ? e0 : NEG_SLOPE * e0;
            float e1 = a1 + adv; e1 = e1 > 0.f ? e1 : NEG_SLOPE * e1;
            float e2 = a2 + adv; e2 = e2 > 0.f ? e2 : NEG_SLOPE * e2;
            float e3 = a3 + adv; e3 = e3 > 0.f ? e3 : NEG_SLOPE * e3;
            float w0 = __expf(e0), w1 = __expf(e1), w2 = __expf(e2), w3 = __expf(e3);
            sum += (w0 + w1) + (w2 + w3);
            float2 l0 = __half22float2(*(const __half2*)&v0.x);
            float2 u0 = __half22float2(*(const __half2*)&v0.y);
            float2 l1 = __half22float2(*(const __half2*)&v1.x);
            float2 u1 = __half22float2(*(const __half2*)&v1.y);
            float2 l2 = __half22float2(*(const __half2*)&v2.x);
            float2 u2 = __half22float2(*(const __half2*)&v2.y);
            float2 l3 = __half22float2(*(const __half2*)&v3.x);
            float2 u3 = __half22float2(*(const __half2*)&v3.y);
            ax = fmaf(w0, l0.x, fmaf(w1, l1.x, fmaf(w2, l2.x, fmaf(w3, l3.x, ax))));
            ay = fmaf(w0, l0.y, fmaf(w1, l1.y, fmaf(w2, l2.y, fmaf(w3, l3.y, ay))));
            az = fmaf(w0, u0.x, fmaf(w1, u1.x, fmaf(w2, u2.x, fmaf(w3, u3.x, az))));
            aw = fmaf(w0, u0.y, fmaf(w1, u1.y, fmaf(w2, u2.y, fmaf(w3, u3.y, aw))));
        }
        for (; j < deg; ++j) {
            int s0 = __ldg(es + j);
            float a0 = g_as[s0 * HEADS + hh];
            uint2 v0 = *(const uint2*)&hbase[(size_t)s0 * HC + lane * 4];
            float e0 = a0 + adv; e0 = e0 > 0.f ? e0 : NEG_SLOPE * e0;
            float w0 = __expf(e0);
            sum += w0;
            float2 l0 = __half22float2(*(const __half2*)&v0.x);
            float2 u0 = __half22float2(*(const __half2*)&v0.y);
            ax = fmaf(w0, l0.x, ax);
            ay = fmaf(w0, l0.y, ay);
            az = fmaf(w0, u0.x, az);
            aw = fmaf(w0, u0.y, aw);
        }
        float inv = 1.0f / sum;
        float4 bv = *(const float4*)&bias[lane * 4];
        xr[warp][lane * 4 + 0] = fmaf(ax, inv, bv.x);
        xr[warp][lane * 4 + 1] = fmaf(ay, inv, bv.y);
        xr[warp][lane * 4 + 2] = fmaf(az, inv, bv.z);
        xr[warp][lane * 4 + 3] = fmaf(aw, inv, bv.w);
        __syncwarp();

        int oc = lane;
        float accv = 0.0f;
        const float* row = xr[warp];
        #pragma unroll 8
        for (int kp = 0; kp < 64; ++kp) {
            float2 wv = __half22float2(Wt2[kp * 32 + oc]);
            accv = fmaf(row[2 * kp], wv.x, accv);
            accv = fmaf(row[2 * kp + 1], wv.y, accv);
        }
        accv += __ldg(&bl[oc]);
        out[(size_t)node * OC + oc] = accv > 0.0f ? accv : (__expf(accv) - 1.0f);
        __syncwarp();   // xr reuse guard before next node
    }
}

// ---------------- launch -----------------------------------------------------
extern "C" void kernel_launch(void* const* d_in, const int* in_sizes, int n_in,
                              void* d_out, int out_size) {
    const float* x     = (const float*)d_in[0];
    const void*  ei    = d_in[1];
    const float* W     = (const float*)d_in[2];
    const float* att_s = (const float*)d_in[3];
    const float* att_d = (const float*)d_in[4];
    const float* bias  = (const float*)d_in[5];
    const float* Wl    = (const float*)d_in[6];
    const float* bl    = (const float*)d_in[7];
    float* out = (float*)d_out;

    int n = in_sizes[0] / INC;
    int e = in_sizes[1] / 2;
    int etot = e + n;
    int nscan = (n + SCAN_BLK - 1) / SCAN_BLK;

    int nb_gemm = (n + 63) / 64;
    int nb_scat = (nb_gemm + 2) / 3;
    int nb_fused = 4 * nb_scat;

    static void* deg_ptr = nullptr;
    static int smem_set = 0;
    if (!smem_set) {
        cudaFuncSetAttribute(k_gemm_scatter, cudaFuncAttributeMaxDynamicSharedMemorySize, 110 * 1024);
        cudaGetSymbolAddress(&deg_ptr, g_deg);
        smem_set = 1;
    }
    size_t gemm_smem = (size_t)(128 * 132 + 128 * XS_STRIDE) * sizeof(float);

    cudaMemsetAsync(deg_ptr, 0, (size_t)n * sizeof(int));
    k_prep<<<(etot + 255) / 256, 256>>>(ei, e, n);
    k_scan1<<<nscan, SCAN_BLK>>>(n);
    k_scan23<<<nscan, SCAN_BLK>>>(n);
    k_gemm_scatter<<<nb_fused, 256, gemm_smem>>>(x, W, att_s, att_d, ei, n, e, nb_gemm, nb_scat);
    k_gather_final<<<GATHER_BLOCKS, 512>>>(bias, Wl, bl, out, n, GATHER_BLOCKS * 16);
}

// round 13
// speedup vs baseline: 1.3143x; 1.0795x over previous
#include <cuda_runtime.h>
#include <cuda_fp16.h>
#include <math.h>

#define NN   100000
#define EE   1600000
#define ETOT (EE + NN)
#define INC  128
#define HC   128     // HEADS*OUT_C
#define OC   32
#define HEADS 4
#define NEG_SLOPE 0.2f
#define SCAN_BLK 256
#define WS_STRIDE 132
#define GATHER_BLOCKS 304   // 2 per SM on 152 SMs

typedef unsigned int uint32;

// ---------------- device scratch (static: no allocations allowed) ----------
__device__ int    g_esrc[ETOT];          // CSR: src ids grouped by dst
__device__ int    g_deg[NN];             // in-degree per node
__device__ int    g_tmp[NN];             // block-local exclusive scan
__device__ int    g_part[1024];          // per-block partial sums
__device__ int    g_rowptr[NN];          // CSR row starts
__device__ int    g_cursor[NN];          // scatter cursors
__device__ __half g_h[NN * HC];          // projected features, fp16 [N,128]
__device__ float  g_as[NN * HEADS];      // per-node src logits (fp32)
__device__ float  g_ad[NN * HEADS];      // per-node dst logits (fp32)

// ---------------- helpers ----------------------------------------------------
__device__ __forceinline__ unsigned int f2h2(float a, float b) {
    __half2 h = __floats2half2_rn(a, b);
    return *(unsigned int*)&h;
}
__device__ __forceinline__ uint32 f2tf32(float v) {
    uint32 u; asm("cvt.rna.tf32.f32 %0, %1;" : "=r"(u) : "f"(v)); return u;
}
__device__ __forceinline__ void mma_tf32(float c[4],
                                         uint32 a0, uint32 a1, uint32 a2, uint32 a3,
                                         uint32 b0, uint32 b1) {
    asm volatile(
        "mma.sync.aligned.m16n8k8.row.col.f32.tf32.tf32.f32 "
        "{%0,%1,%2,%3}, {%4,%5,%6,%7}, {%8,%9}, {%0,%1,%2,%3};"
        : "+f"(c[0]), "+f"(c[1]), "+f"(c[2]), "+f"(c[3])
        : "r"(a0), "r"(a1), "r"(a2), "r"(a3), "r"(b0), "r"(b1));
}

// per-call dtype detection: reads first 64 entries as int64; all-valid => i64
__device__ __forceinline__ int detect64(const void* ei) {
    const long long* p = (const long long*)ei;
    int ok = 1;
    #pragma unroll 1
    for (int q = 0; q < 64; ++q) {
        long long v = p[q];
        if (!(v >= 0 && v < (long long)NN)) { ok = 0; break; }
    }
    return ok;
}

// ---------------- histogram in-degrees --------------------------------------
__global__ void k_prep(const void* ei, int e, int n) {
    int is64 = detect64(ei);
    int i = blockIdx.x * blockDim.x + threadIdx.x;
    int tot = e + n;
    if (i >= tot) return;
    int d;
    if (i < e) {
        if (is64) d = (int)((const long long*)ei)[e + i];
        else      d = ((const int*)ei)[e + i];
    } else {
        d = i - e;
    }
    atomicAdd(&g_deg[d], 1);
}

// ---------------- scan stage 1 ----------------------------------------------
__global__ void k_scan1(int n) {
    __shared__ int sm[SCAN_BLK];
    int t = threadIdx.x;
    int i = blockIdx.x * SCAN_BLK + t;
    int v = (i < n) ? g_deg[i] : 0;
    sm[t] = v;
    __syncthreads();
    #pragma unroll
    for (int off = 1; off < SCAN_BLK; off <<= 1) {
        int u = (t >= off) ? sm[t - off] : 0;
        __syncthreads();
        sm[t] += u;
        __syncthreads();
    }
    if (i < n) g_tmp[i] = sm[t] - v;
    if (t == SCAN_BLK - 1) g_part[blockIdx.x] = sm[t];
}

// ---------------- scan stage 2+3 --------------------------------------------
__global__ void k_scan23(int n) {
    __shared__ int sm[SCAN_BLK];
    int b = blockIdx.x, t = threadIdx.x;
    int acc = 0;
    for (int j = t; j < b; j += SCAN_BLK) acc += g_part[j];
    sm[t] = acc;
    __syncthreads();
    #pragma unroll
    for (int off = SCAN_BLK / 2; off > 0; off >>= 1) {
        if (t < off) sm[t] += sm[t + off];
        __syncthreads();
    }
    int base = sm[0];
    int i = b * SCAN_BLK + t;
    if (i < n) {
        int r = g_tmp[i] + base;
        g_rowptr[i] = r;
        g_cursor[i] = r;
    }
}

// ---------------- fused tf32-MMA GEMM (+logits) || CSR scatter ---------------
// gemm role: 256 thr = 8 warps (4 m-tiles x 2 n-halves), 64 rows x 128 cols.
// mma.sync m16n8k8 tf32 on the tensor pipe; fp32 accumulate.
// scatter role: grid-stride atomic-cursor CSR build (bid%4==3).
__global__ void __launch_bounds__(256)
k_gemm_scatter(const float* __restrict__ x, const float* __restrict__ W,
               const float* __restrict__ att_s, const float* __restrict__ att_d,
               const void* ei, int n, int e,
               int nb_gemm, int nb_scat) {
    int bid = blockIdx.x;
    int tid = threadIdx.x;

    if ((bid & 3) == 3) {
        int sid = bid >> 2;
        if (sid >= nb_scat) return;
        int is64 = detect64(ei);
        int etot = e + n;
        int stride = nb_scat * 256;
        for (int i = sid * 256 + tid; i < etot; i += stride) {
            int s, d;
            if (i < e) {
                if (is64) {
                    const long long* p = (const long long*)ei;
                    s = (int)p[i];
                    d = (int)p[e + i];
                } else {
                    const int* p = (const int*)ei;
                    s = p[i];
                    d = p[e + i];
                }
            } else {
                s = d = i - e;
            }
            int pos = atomicAdd(&g_cursor[d], 1);
            g_esrc[pos] = s;
        }
        return;
    }

    int gid = (bid >> 2) * 3 + (bid & 3);
    if (gid >= nb_gemm) return;

    extern __shared__ uint32 smu[];
    uint32* Ws = smu;                      // [128][132] tf32, Ws[nrow*132 + k]
    uint32* xs = smu + 128 * WS_STRIDE;    // [64][132]  tf32, xs[r*132 + k]

    // stage W (coalesced read, conflict-free write: consecutive k -> consec banks)
    for (int idx = tid; idx < HC * INC; idx += 256) {
        int nr = idx >> 7, k = idx & 127;
        Ws[nr * WS_STRIDE + k] = f2tf32(W[idx]);
    }
    int row0 = gid * 64;
    for (int idx = tid; idx < 64 * INC; idx += 256) {
        int r = idx >> 7, k = idx & 127;
        float v = (row0 + r < n) ? x[(size_t)row0 * INC + idx] : 0.0f;
        xs[r * WS_STRIDE + k] = f2tf32(v);
    }
    __syncthreads();

    int w    = tid >> 5;
    int lane = tid & 31;
    int qr   = lane >> 2;      // quad row  (0..7)
    int qc   = lane & 3;       // quad col  (0..3)
    int m0   = (w & 3) * 16;   // warp m-tile
    int n0   = (w >> 2) * 64;  // warp n-half

    float acc[8][4];
    #pragma unroll
    for (int nt = 0; nt < 8; ++nt)
        #pragma unroll
        for (int c = 0; c < 4; ++c) acc[nt][c] = 0.0f;

    const uint32* xbase = &xs[(m0 + qr) * WS_STRIDE + qc];
    const uint32* wbase = &Ws[(n0 + qr) * WS_STRIDE + qc];

    #pragma unroll 4
    for (int ks = 0; ks < 16; ++ks) {
        int k0 = ks * 8;
        uint32 a0 = xbase[k0];
        uint32 a2 = xbase[k0 + 4];
        uint32 a1 = xbase[k0 + 8 * WS_STRIDE];
        uint32 a3 = xbase[k0 + 8 * WS_STRIDE + 4];
        #pragma unroll
        for (int nt = 0; nt < 8; ++nt) {
            uint32 b0 = wbase[nt * 8 * WS_STRIDE + k0];
            uint32 b1 = wbase[nt * 8 * WS_STRIDE + k0 + 4];
            mma_tf32(acc[nt], a0, a1, a2, a3, b0, b1);
        }
    }

    // epilogue: store fp16 h + fused per-head logits
    int r0 = row0 + m0 + qr;       // rows for c0/c1
    int r1 = r0 + 8;               // rows for c2/c3
    int h0 = n0 >> 5;              // first head of this n-half
    float ps[2][2] = {{0, 0}, {0, 0}};   // [head-in-half][rowgroup]
    float pd[2][2] = {{0, 0}, {0, 0}};

    #pragma unroll
    for (int nt = 0; nt < 8; ++nt) {
        int cb = n0 + nt * 8 + 2 * qc;
        if (r0 < n) *(unsigned int*)&g_h[(size_t)r0 * HC + cb] = f2h2(acc[nt][0], acc[nt][1]);
        if (r1 < n) *(unsigned int*)&g_h[(size_t)r1 * HC + cb] = f2h2(acc[nt][2], acc[nt][3]);
        float as0 = __ldg(&att_s[cb]),  as1 = __ldg(&att_s[cb + 1]);
        float ad0 = __ldg(&att_d[cb]),  ad1 = __ldg(&att_d[cb + 1]);
        int hi = nt >> 2;              // head index within the half
        ps[hi][0] += acc[nt][0] * as0 + acc[nt][1] * as1;
        ps[hi][1] += acc[nt][2] * as0 + acc[nt][3] * as1;
        pd[hi][0] += acc[nt][0] * ad0 + acc[nt][1] * ad1;
        pd[hi][1] += acc[nt][2] * ad0 + acc[nt][3] * ad1;
    }
    #pragma unroll
    for (int hi = 0; hi < 2; ++hi)
        #pragma unroll
        for (int gp = 0; gp < 2; ++gp) {
            #pragma unroll
            for (int o = 1; o <= 2; o <<= 1) {
                ps[hi][gp] += __shfl_xor_sync(0xffffffffu, ps[hi][gp], o);
                pd[hi][gp] += __shfl_xor_sync(0xffffffffu, pd[hi][gp], o);
            }
        }
    if (qc == 0) {
        #pragma unroll
        for (int hi = 0; hi < 2; ++hi) {
            if (r0 < n) { g_as[r0 * HEADS + h0 + hi] = ps[hi][0]; g_ad[r0 * HEADS + h0 + hi] = pd[hi][0]; }
            if (r1 < n) { g_as[r1 * HEADS + h0 + hi] = ps[hi][1]; g_ad[r1 * HEADS + h0 + hi] = pd[hi][1]; }
        }
    }
}

// ---------------- persistent fused gather + final linear ---------------------
__global__ void __launch_bounds__(512, 2)
k_gather_final(const float* __restrict__ bias,
               const float* __restrict__ Wl,
               const float* __restrict__ bl,
               float* __restrict__ out, int n, int nwarps) {
    __shared__ __half2 Wt2[64 * 32];  // Wt2[kp*32+oc]
    __shared__ float xr[16][128];
    int tid  = threadIdx.x;
    int warp = tid >> 5;
    int lane = tid & 31;
    int gw   = blockIdx.x * 16 + warp;

    for (int idx = tid; idx < OC * HC / 2; idx += 512) {
        int oc = idx >> 6;
        int kp = idx & 63;
        Wt2[kp * 32 + oc] = __floats2half2_rn(Wl[oc * HC + 2 * kp],
                                              Wl[oc * HC + 2 * kp + 1]);
    }
    __syncthreads();

    int hh = lane >> 3;
    const __half* hbase = g_h;

    for (int node = gw; node < n; node += nwarps) {
        int start = g_rowptr[node];
        int deg   = g_deg[node];
        float adv = g_ad[node * HEADS + hh];
        const int* es = &g_esrc[start];

        float sum = 0.0f;
        float ax = 0.f, ay = 0.f, az = 0.f, aw = 0.f;
        int j = 0;
        for (; j + 4 <= deg; j += 4) {
            int s0 = __ldg(es + j), s1 = __ldg(es + j + 1);
            int s2 = __ldg(es + j + 2), s3 = __ldg(es + j + 3);
            float a0 = g_as[s0 * HEADS + hh];
            float a1 = g_as[s1 * HEADS + hh];
            float a2 = g_as[s2 * HEADS + hh];
            float a3 = g_as[s3 * HEADS + hh];
            uint2 v0 = *(const uint2*)&hbase[(size_t)s0 * HC + lane * 4];
            uint2 v1 = *(const uint2*)&hbase[(size_t)s1 * HC + lane * 4];
            uint2 v2 = *(const uint2*)&hbase[(size_t)s2 * HC + lane * 4];
            uint2 v3 = *(const uint2*)&hbase[(size_t)s3 * HC + lane * 4];
            float e0 = a0 + adv; e0 = e0 > 0.f ? e0 : NEG_SLOPE * e0;
            float e1 = a1 + adv; e1 = e1 > 0.f ? e1 : NEG_SLOPE * e1;
            float e2 = a2 + adv; e2 = e2 > 0.f ? e2 : NEG_SLOPE * e2;
            float e3 = a3 + adv; e3 = e3 > 0.f ? e3 : NEG_SLOPE * e3;
            float w0 = __expf(e0), w1 = __expf(e1), w2 = __expf(e2), w3 = __expf(e3);
            sum += (w0 + w1) + (w2 + w3);
            float2 l0 = __half22float2(*(const __half2*)&v0.x);
            float2 u0 = __half22float2(*(const __half2*)&v0.y);
            float2 l1 = __half22float2(*(const __half2*)&v1.x);
            float2 u1 = __half22float2(*(const __half2*)&v1.y);
            float2 l2 = __half22float2(*(const __half2*)&v2.x);
            float2 u2 = __half22float2(*(const __half2*)&v2.y);
            float2 l3 = __half22float2(*(const __half2*)&v3.x);
            float2 u3 = __half22float2(*(const __half2*)&v3.y);
            ax = fmaf(w0, l0.x, fmaf(w1, l1.x, fmaf(w2, l2.x, fmaf(w3, l3.x, ax))));
            ay = fmaf(w0, l0.y, fmaf(w1, l1.y, fmaf(w2, l2.y, fmaf(w3, l3.y, ay))));
            az = fmaf(w0, u0.x, fmaf(w1, u1.x, fmaf(w2, u2.x, fmaf(w3, u3.x, az))));
            aw = fmaf(w0, u0.y, fmaf(w1, u1.y, fmaf(w2, u2.y, fmaf(w3, u3.y, aw))));
        }
        for (; j < deg; ++j) {
            int s0 = __ldg(es + j);
            float a0 = g_as[s0 * HEADS + hh];
            uint2 v0 = *(const uint2*)&hbase[(size_t)s0 * HC + lane * 4];
            float e0 = a0 + adv; e0 = e0 > 0.f ? e0 : NEG_SLOPE * e0;
            float w0 = __expf(e0);
            sum += w0;
            float2 l0 = __half22float2(*(const __half2*)&v0.x);
            float2 u0 = __half22float2(*(const __half2*)&v0.y);
            ax = fmaf(w0, l0.x, ax);
            ay = fmaf(w0, l0.y, ay);
            az = fmaf(w0, u0.x, az);
            aw = fmaf(w0, u0.y, aw);
        }
        float inv = 1.0f / sum;
        float4 bv = *(const float4*)&bias[lane * 4];
        xr[warp][lane * 4 + 0] = fmaf(ax, inv, bv.x);
        xr[warp][lane * 4 + 1] = fmaf(ay, inv, bv.y);
        xr[warp][lane * 4 + 2] = fmaf(az, inv, bv.z);
        xr[warp][lane * 4 + 3] = fmaf(aw, inv, bv.w);
        __syncwarp();

        int oc = lane;
        float accv = 0.0f;
        const float* row = xr[warp];
        #pragma unroll 8
        for (int kp = 0; kp < 64; ++kp) {
            float2 wv = __half22float2(Wt2[kp * 32 + oc]);
            accv = fmaf(row[2 * kp], wv.x, accv);
            accv = fmaf(row[2 * kp + 1], wv.y, accv);
        }
        accv += __ldg(&bl[oc]);
        out[(size_t)node * OC + oc] = accv > 0.0f ? accv : (__expf(accv) - 1.0f);
        __syncwarp();   // xr reuse guard before next node
    }
}

// ---------------- launch -----------------------------------------------------
extern "C" void kernel_launch(void* const* d_in, const int* in_sizes, int n_in,
                              void* d_out, int out_size) {
    const float* x     = (const float*)d_in[0];
    const void*  ei    = d_in[1];
    const float* W     = (const float*)d_in[2];
    const float* att_s = (const float*)d_in[3];
    const float* att_d = (const float*)d_in[4];
    const float* bias  = (const float*)d_in[5];
    const float* Wl    = (const float*)d_in[6];
    const float* bl    = (const float*)d_in[7];
    float* out = (float*)d_out;

    int n = in_sizes[0] / INC;
    int e = in_sizes[1] / 2;
    int etot = e + n;
    int nscan = (n + SCAN_BLK - 1) / SCAN_BLK;

    int nb_gemm = (n + 63) / 64;
    int nb_scat = (nb_gemm + 2) / 3;
    int nb_fused = 4 * nb_scat;

    static void* deg_ptr = nullptr;
    static int smem_set = 0;
    if (!smem_set) {
        cudaFuncSetAttribute(k_gemm_scatter, cudaFuncAttributeMaxDynamicSharedMemorySize, 110 * 1024);
        cudaGetSymbolAddress(&deg_ptr, g_deg);
        smem_set = 1;
    }
    size_t gemm_smem = (size_t)(128 * WS_STRIDE + 64 * WS_STRIDE) * sizeof(uint32);

    cudaMemsetAsync(deg_ptr, 0, (size_t)n * sizeof(int));
    k_prep<<<(etot + 255) / 256, 256>>>(ei, e, n);
    k_scan1<<<nscan, SCAN_BLK>>>(n);
    k_scan23<<<nscan, SCAN_BLK>>>(n);
    k_gemm_scatter<<<nb_fused, 256, gemm_smem>>>(x, W, att_s, att_d, ei, n, e, nb_gemm, nb_scat);
    k_gather_final<<<GATHER_BLOCKS, 512>>>(bias, Wl, bl, out, n, GATHER_BLOCKS * 16);
}